// round 4
// baseline (speedup 1.0000x reference)
#include <cuda_runtime.h>
#include <cuda_bf16.h>

#define TB    256
#define NTOK  32768          // 16 * 2048
#define TOKT  2048
#define FD    64
#define AL    48
#define GRID1 148

// scratch: raw attention scores, scores[g*AL + a]  (only a < L slots written/read)
__device__ float g_scores[(size_t)NTOK * AL];

__device__ __forceinline__ float sigmoidf_fast(float x) {
    return __fdividef(1.0f, 1.0f + __expf(-x));
}

extern __shared__ float4 s_dyn[];

// ---------------- Kernel 1: recurrent scan + score computation ----------------
// thread-per-token. H lives in registers (all indices compile-time).
// Hn writes (dynamic output index) go through shared memory, transposed layout.
__global__ void __launch_bounds__(TB, 1)
scan_score_kernel(const float* __restrict__ he,
                  const float* __restrict__ gW1,
                  const float* __restrict__ gW2)
{
    float4* sW1 = s_dyn;                     // 1024 float4 = 16 KB
    float4* sW2 = s_dyn + 1024;              // 16 KB
    float*  sHn = (float*)(s_dyn + 2048);    // TB * 64 floats = 64 KB

    const int tid = threadIdx.x;
    {
        const float4* w1v = (const float4*)gW1;
        const float4* w2v = (const float4*)gW2;
        #pragma unroll
        for (int i = 0; i < 1024 / TB; ++i) {
            sW1[tid + i * TB] = w1v[tid + i * TB];
            sW2[tid + i * TB] = w2v[tid + i * TB];
        }
    }
    __syncthreads();

    // transposed token map: every SM gets ~221 tokens -> full-chip balance
    const int g = tid * GRID1 + blockIdx.x;
    if (g >= NTOK) return;

    const int t = g & (TOKT - 1);
    const float* bbase = he + (size_t)(g - t) * FD;
    const int L = min(AL, max(t, 1));

    float H[FD];
    {
        const float4* hr = (const float4*)(he + (size_t)g * FD);
        #pragma unroll
        for (int i = 0; i < FD / 4; ++i) {
            float4 v = hr[i];
            H[4*i+0] = v.x; H[4*i+1] = v.y; H[4*i+2] = v.z; H[4*i+3] = v.w;
        }
    }

    float* myHn = sHn + tid;    // stride TB between feature rows, conflict-free

    #pragma unroll 1
    for (int a = 0; a < AL; ++a) {
        // ---- Hn = sigmoid(H @ W1), written to smem (dynamic c4 loop) ----
        #pragma unroll 1
        for (int c4 = 0; c4 < FD / 4; ++c4) {
            float a0 = 0.f, a1 = 0.f, a2 = 0.f, a3 = 0.f;
            #pragma unroll
            for (int k = 0; k < FD; ++k) {
                float4 w = sW1[k * (FD / 4) + c4];
                float  h = H[k];
                a0 = fmaf(h, w.x, a0);
                a1 = fmaf(h, w.y, a1);
                a2 = fmaf(h, w.z, a2);
                a3 = fmaf(h, w.w, a3);
            }
            myHn[(4*c4+0) * TB] = sigmoidf_fast(a0);
            myHn[(4*c4+1) * TB] = sigmoidf_fast(a1);
            myHn[(4*c4+2) * TB] = sigmoidf_fast(a2);
            myHn[(4*c4+3) * TB] = sigmoidf_fast(a3);
        }
        // copy back into registers (compile-time indices)
        #pragma unroll
        for (int k = 0; k < FD; ++k) H[k] = myHn[k * TB];

        if (a < L) {
            // ---- score = < sigmoid(H @ W2), he[b, j, :] >  (Y never materialized) ----
            int j = t - L + a;
            if (j < 0) j = 0;
            const float4* row = (const float4*)(bbase + (size_t)j * FD);

            float sc = 0.f;
            #pragma unroll 1
            for (int c4 = 0; c4 < FD / 4; ++c4) {
                float4 rv = row[c4];          // issued early, hidden under matvec chunk
                float a0 = 0.f, a1 = 0.f, a2 = 0.f, a3 = 0.f;
                #pragma unroll
                for (int k = 0; k < FD; ++k) {
                    float4 w = sW2[k * (FD / 4) + c4];
                    float  h = H[k];
                    a0 = fmaf(h, w.x, a0);
                    a1 = fmaf(h, w.y, a1);
                    a2 = fmaf(h, w.z, a2);
                    a3 = fmaf(h, w.w, a3);
                }
                sc = fmaf(sigmoidf_fast(a0), rv.x, sc);
                sc = fmaf(sigmoidf_fast(a1), rv.y, sc);
                sc = fmaf(sigmoidf_fast(a2), rv.z, sc);
                sc = fmaf(sigmoidf_fast(a3), rv.w, sc);
            }
            g_scores[(size_t)g * AL + a] = sc;
        }
    }
}

// ---------------- Kernel 2: softmax over scores + weighted gather ----------------
__global__ void __launch_bounds__(TB, 1)
attn_kernel(const float* __restrict__ he, float* __restrict__ out)
{
    const int g = blockIdx.x * TB + threadIdx.x;
    const int t = g & (TOKT - 1);
    const float* bbase = he + (size_t)(g - t) * FD;
    const int L = min(AL, max(t, 1));
    const float* sc = g_scores + (size_t)g * AL;

    float m = -1e30f;
    #pragma unroll 1
    for (int a = 0; a < L; ++a) m = fmaxf(m, sc[a]);

    float ssum = 0.f;
    float ctx[FD];
    #pragma unroll
    for (int f = 0; f < FD; ++f) ctx[f] = 0.f;

    #pragma unroll 1
    for (int a = 0; a < L; ++a) {
        float p = __expf(sc[a] - m);
        ssum += p;
        int j = t - L + a;
        if (j < 0) j = 0;
        const float4* row = (const float4*)(bbase + (size_t)j * FD);
        #pragma unroll
        for (int i = 0; i < FD / 4; ++i) {
            float4 v = row[i];
            ctx[4*i+0] = fmaf(p, v.x, ctx[4*i+0]);
            ctx[4*i+1] = fmaf(p, v.y, ctx[4*i+1]);
            ctx[4*i+2] = fmaf(p, v.z, ctx[4*i+2]);
            ctx[4*i+3] = fmaf(p, v.w, ctx[4*i+3]);
        }
    }

    const float inv = __fdividef(1.0f, ssum);
    float4* o = (float4*)(out + (size_t)g * FD);
    #pragma unroll
    for (int i = 0; i < FD / 4; ++i) {
        float4 v;
        v.x = ctx[4*i+0] * inv;
        v.y = ctx[4*i+1] * inv;
        v.z = ctx[4*i+2] * inv;
        v.w = ctx[4*i+3] * inv;
        o[i] = v;
    }
}

extern "C" void kernel_launch(void* const* d_in, const int* in_sizes, int n_in,
                              void* d_out, int out_size)
{
    const float* he = (const float*)d_in[0];   // (16, 2048, 64) f32
    const float* W1 = (const float*)d_in[1];   // (64, 64) f32
    const float* W2 = (const float*)d_in[2];   // (64, 64) f32
    float* out = (float*)d_out;                // (16, 2048, 64) f32

    const int smem1 = 2 * 1024 * 16 + TB * FD * 4;   // 32 KB W + 64 KB Hn = 96 KB
    cudaFuncSetAttribute(scan_score_kernel,
                         cudaFuncAttributeMaxDynamicSharedMemorySize, smem1);

    scan_score_kernel<<<GRID1, TB, smem1>>>(he, W1, W2);
    attn_kernel<<<NTOK / TB, TB>>>(he, out);
}

// round 5
// speedup vs baseline: 1.2393x; 1.2393x over previous
#include <cuda_runtime.h>
#include <cuda_bf16.h>

#define TB    224            // 7 warps; grid 148 -> ~222 tokens/CTA, lane eff ~99%
#define NTOK  32768          // 16 * 2048
#define TOKT  2048
#define FD    64
#define AL    48
#define GRID1 148

#define TB2   128            // attn kernel: 128 tokens per CTA
#define RSTRIDE 68           // padded row stride (floats) -> 4-way LDS conflict max

// scratch: raw attention scores, scores[g*AL + a]  (only a < L slots written)
__device__ float g_scores[(size_t)NTOK * AL];

typedef unsigned long long ull;

__device__ __forceinline__ float sigmoidf_fast(float x) {
    return __fdividef(1.0f, 1.0f + __expf(-x));
}
__device__ __forceinline__ ull pack2(float x, float y) {
    ull r; asm("mov.b64 %0, {%1, %2};" : "=l"(r) : "f"(x), "f"(y)); return r;
}
__device__ __forceinline__ void unpack2(ull v, float& x, float& y) {
    asm("mov.b64 {%0, %1}, %2;" : "=f"(x), "=f"(y) : "l"(v));
}
// packed double-rate fp32 FMA (sm_103a FFMA2) — only reachable via PTX f32x2
__device__ __forceinline__ void ffma2(ull& d, ull a, ull b) {
    asm("fma.rn.f32x2 %0, %1, %2, %0;" : "+l"(d) : "l"(a), "l"(b));
}

extern __shared__ float s_dyn[];

// ---------------- Kernel 1: recurrent scan + score computation ----------------
// thread-per-token, H in registers as 32 packed f32x2 pairs (k-pair packing).
// W1/W2 transposed in shared (column-major) so LDS.128 yields two k-pairs.
__global__ void __launch_bounds__(TB, 1)
scan_score_kernel(const float* __restrict__ he,
                  const float* __restrict__ gW1,
                  const float* __restrict__ gW2)
{
    float* sWt1 = s_dyn;                 // [64 cols][64 k]  16 KB
    float* sWt2 = s_dyn + 4096;          // 16 KB
    ull*   sHn  = (ull*)(s_dyn + 8192);  // [32 pairs][TB]   56 KB

    const int tid = threadIdx.x;
    // transpose weights into shared: sWt[c*64 + k] = W[k*64 + c]
    for (int i = tid; i < 4096; i += TB) {
        int k = i >> 6, c = i & 63;      // coalesced global read
        sWt1[c * 64 + k] = gW1[i];
        sWt2[c * 64 + k] = gW2[i];
    }
    __syncthreads();

    const int g = tid * GRID1 + blockIdx.x;   // transposed token map
    if (g >= NTOK) return;

    const int t = g & (TOKT - 1);
    const float* bbase = he + (size_t)(g - t) * FD;
    const int L = min(AL, max(t, 1));

    // H as 32 packed pairs: Hp[p] = {H[2p], H[2p+1]}
    ull Hp[FD / 2];
    {
        const float4* hr = (const float4*)(he + (size_t)g * FD);
        #pragma unroll
        for (int i = 0; i < FD / 4; ++i) {
            float4 v = hr[i];
            Hp[2*i+0] = pack2(v.x, v.y);
            Hp[2*i+1] = pack2(v.z, v.w);
        }
    }

    #pragma unroll 1
    for (int a = 0; a < AL; ++a) {
        // ---- Hn = sigmoid(H @ W1) ----
        #pragma unroll 1
        for (int c8 = 0; c8 < 8; ++c8) {            // 8 columns per chunk
            ull acc[8];
            #pragma unroll
            for (int c = 0; c < 8; ++c) acc[c] = 0ull;
            const ulonglong2* wb = (const ulonglong2*)(sWt1 + (c8 * 8) * 64);
            #pragma unroll
            for (int q = 0; q < 16; ++q) {          // 4 k-values per q
                #pragma unroll
                for (int c = 0; c < 8; ++c) {
                    ulonglong2 w = wb[c * 16 + q];  // {W[4q],W[4q+1]},{W[4q+2],W[4q+3]}
                    ffma2(acc[c], Hp[2*q],   w.x);
                    ffma2(acc[c], Hp[2*q+1], w.y);
                }
            }
            #pragma unroll
            for (int c = 0; c < 8; c += 2) {        // cross-add + sigmoid, pair store
                float x0, y0, x1, y1;
                unpack2(acc[c],   x0, y0);
                unpack2(acc[c+1], x1, y1);
                sHn[(c8 * 4 + (c >> 1)) * TB + tid] =
                    pack2(sigmoidf_fast(x0 + y0), sigmoidf_fast(x1 + y1));
            }
        }
        // reload H pairs (same thread, same addresses — no sync needed)
        #pragma unroll
        for (int p = 0; p < FD / 2; ++p) Hp[p] = sHn[p * TB + tid];

        if (a < L) {
            // ---- score = < sigmoid(H @ W2), he[b, j, :] > ----
            int j = t - L + a;
            if (j < 0) j = 0;
            const float4* row = (const float4*)(bbase + (size_t)j * FD);

            float sc = 0.f;
            #pragma unroll 1
            for (int c8 = 0; c8 < 8; ++c8) {
                ull acc[8];
                #pragma unroll
                for (int c = 0; c < 8; ++c) acc[c] = 0ull;
                float4 rv0 = row[c8 * 2];
                float4 rv1 = row[c8 * 2 + 1];
                const ulonglong2* wb = (const ulonglong2*)(sWt2 + (c8 * 8) * 64);
                #pragma unroll
                for (int q = 0; q < 16; ++q) {
                    #pragma unroll
                    for (int c = 0; c < 8; ++c) {
                        ulonglong2 w = wb[c * 16 + q];
                        ffma2(acc[c], Hp[2*q],   w.x);
                        ffma2(acc[c], Hp[2*q+1], w.y);
                    }
                }
                float x, y;
                unpack2(acc[0], x, y); sc = fmaf(sigmoidf_fast(x + y), rv0.x, sc);
                unpack2(acc[1], x, y); sc = fmaf(sigmoidf_fast(x + y), rv0.y, sc);
                unpack2(acc[2], x, y); sc = fmaf(sigmoidf_fast(x + y), rv0.z, sc);
                unpack2(acc[3], x, y); sc = fmaf(sigmoidf_fast(x + y), rv0.w, sc);
                unpack2(acc[4], x, y); sc = fmaf(sigmoidf_fast(x + y), rv1.x, sc);
                unpack2(acc[5], x, y); sc = fmaf(sigmoidf_fast(x + y), rv1.y, sc);
                unpack2(acc[6], x, y); sc = fmaf(sigmoidf_fast(x + y), rv1.z, sc);
                unpack2(acc[7], x, y); sc = fmaf(sigmoidf_fast(x + y), rv1.w, sc);
            }
            g_scores[(size_t)g * AL + a] = sc;
        }
    }
}

// ---------------- Kernel 2: softmax + weighted gather via shared row tile ----
__global__ void __launch_bounds__(TB2, 1)
attn_kernel(const float* __restrict__ he, float* __restrict__ out)
{
    __shared__ float srows[175 * RSTRIDE];   // 47.6 KB: row window, padded stride

    const int tid   = threadIdx.x;
    const int t0g   = blockIdx.x * TB2;          // first global token of this CTA
    const int tseq0 = t0g & (TOKT - 1);          // block never straddles a batch
    const float* bbase = he + (size_t)(t0g - tseq0) * FD;

    const int r0    = max(0, tseq0 - AL);        // first row needed
    const int r1    = tseq0 + TB2 - 2;           // last row needed (j <= t-1)
    const int nrows = r1 - r0 + 1;               // <= 175

    // coalesced load of the row window into padded shared
    {
        const float4* src = (const float4*)(bbase + (size_t)r0 * FD);
        float4* dst = (float4*)srows;            // row r at float4 index r*17
        for (int i = tid; i < nrows * 16; i += TB2) {
            int r = i >> 4, q = i & 15;
            dst[r * 17 + q] = src[r * 16 + q];
        }
    }
    __syncthreads();

    const int g = t0g + tid;
    const int t = tseq0 + tid;
    const int L = min(AL, max(t, 1));
    const float* scp = g_scores + (size_t)g * AL;

    float s[AL];
    #pragma unroll
    for (int a = 0; a < AL; ++a) {
        float v = scp[a];
        s[a] = (a < L) ? v : -1e30f;             // masked slots -> exp underflows to 0
    }
    float m = -1e30f;
    #pragma unroll
    for (int a = 0; a < AL; ++a) m = fmaxf(m, s[a]);

    ull cpair[FD / 2];
    #pragma unroll
    for (int p = 0; p < FD / 2; ++p) cpair[p] = 0ull;
    float ssum = 0.f;

    #pragma unroll 4
    for (int a = 0; a < AL; ++a) {
        float p = __expf(s[a] - m);              // exactly 0 for masked a
        ssum += p;
        int j = t - L + a;
        j = min(max(j, 0), r1);                  // clamp (masked lanes only)
        const ulonglong2* rp = (const ulonglong2*)(srows + (j - r0) * RSTRIDE);
        ull pp = pack2(p, p);
        #pragma unroll
        for (int q = 0; q < 16; ++q) {
            ulonglong2 v = rp[q];
            ffma2(cpair[2*q],   pp, v.x);
            ffma2(cpair[2*q+1], pp, v.y);
        }
    }

    const float inv = __fdividef(1.0f, ssum);
    float4* o = (float4*)(out + (size_t)g * FD);
    #pragma unroll
    for (int i = 0; i < FD / 4; ++i) {
        float x0, y0, x1, y1;
        unpack2(cpair[2*i],   x0, y0);
        unpack2(cpair[2*i+1], x1, y1);
        float4 v;
        v.x = x0 * inv; v.y = y0 * inv; v.z = x1 * inv; v.w = y1 * inv;
        o[i] = v;
    }
}

extern "C" void kernel_launch(void* const* d_in, const int* in_sizes, int n_in,
                              void* d_out, int out_size)
{
    const float* he = (const float*)d_in[0];   // (16, 2048, 64) f32
    const float* W1 = (const float*)d_in[1];   // (64, 64) f32
    const float* W2 = (const float*)d_in[2];   // (64, 64) f32
    float* out = (float*)d_out;                // (16, 2048, 64) f32

    const int smem1 = 4096 * 4 * 2 + 32 * TB * 8;   // 32 KB Wt + 56 KB Hn = 88 KB
    cudaFuncSetAttribute(scan_score_kernel,
                         cudaFuncAttributeMaxDynamicSharedMemorySize, smem1);

    scan_score_kernel<<<GRID1, TB, smem1>>>(he, W1, W2);
    attn_kernel<<<NTOK / TB2, TB2>>>(he, out);
}

// round 7
// speedup vs baseline: 4.1623x; 3.3585x over previous
#include <cuda_runtime.h>
#include <cuda_bf16.h>
#include <cstdint>

#define NTOK  32768
#define TOKT  2048
#define FD    64
#define AL    48
#define THREADS 256
#define GRID1 148
#define NTILES (NTOK / 32)     // 1024 warp tiles

#define TB2    128
#define RSTRIDE 68

typedef unsigned long long ull;

__device__ float g_scores[(size_t)NTOK * AL];

// ---------------- helpers ----------------
__device__ __forceinline__ float sigmoidf_fast(float x) {
    return __fdividef(1.0f, 1.0f + __expf(-x));
}
__device__ __forceinline__ uint32_t pack_bf16x2(float lo, float hi) {
    // dest low 16 bits <- second src operand (PTX cvt.f16x2/bf16x2 semantics)
    uint32_t r;
    asm("cvt.rn.bf16x2.f32 %0, %1, %2;" : "=r"(r) : "f"(hi), "f"(lo));
    return r;
}
__device__ __forceinline__ float bf_lo(uint32_t p) { return __uint_as_float(p << 16); }
__device__ __forceinline__ float bf_hi(uint32_t p) { return __uint_as_float(p & 0xFFFF0000u); }

// split two f32 into bf16x2 hi-pack + bf16x2 lo-residual-pack
__device__ __forceinline__ void split_pair(float d0, float d1, uint32_t& hi, uint32_t& lo) {
    hi = pack_bf16x2(d0, d1);
    lo = pack_bf16x2(d0 - bf_lo(hi), d1 - bf_hi(hi));
}

__device__ __forceinline__ void mma_acc(float* d, const uint32_t* a, uint32_t b0, uint32_t b1) {
    asm volatile("mma.sync.aligned.m16n8k16.row.col.f32.bf16.bf16.f32 "
        "{%0,%1,%2,%3}, {%4,%5,%6,%7}, {%8,%9}, {%0,%1,%2,%3};"
        : "+f"(d[0]), "+f"(d[1]), "+f"(d[2]), "+f"(d[3])
        : "r"(a[0]), "r"(a[1]), "r"(a[2]), "r"(a[3]), "r"(b0), "r"(b1));
}
__device__ __forceinline__ void mma_zero(float* d, const uint32_t* a, uint32_t b0, uint32_t b1) {
    asm volatile("mma.sync.aligned.m16n8k16.row.col.f32.bf16.bf16.f32 "
        "{%0,%1,%2,%3}, {%4,%5,%6,%7}, {%8,%9}, {%10,%10,%10,%10};"
        : "=f"(d[0]), "=f"(d[1]), "=f"(d[2]), "=f"(d[3])
        : "r"(a[0]), "r"(a[1]), "r"(a[2]), "r"(a[3]), "r"(b0), "r"(b1), "f"(0.0f));
}

__device__ __forceinline__ ull pack2(float x, float y) {
    ull r; asm("mov.b64 %0, {%1, %2};" : "=l"(r) : "f"(x), "f"(y)); return r;
}
__device__ __forceinline__ void unpack2(ull v, float& x, float& y) {
    asm("mov.b64 {%0, %1}, %2;" : "=f"(x), "=f"(y) : "l"(v));
}
__device__ __forceinline__ void ffma2(ull& d, ull a, ull b) {
    asm("fma.rn.f32x2 %0, %1, %2, %0;" : "+l"(d) : "l"(a), "l"(b));
}

// ---------------- Kernel 1: recurrent scan via mma.sync bf16x3 ----------------
// warp owns 32 consecutive tokens (M=32): 2 m-tiles x 8 n-tiles of m16n8k16.
// H lives in A fragments (hi+lo bf16); W1/W2 hi/lo B fragments in smem.
__global__ void __launch_bounds__(THREADS, 1)
scan_mma_kernel(const float* __restrict__ he,
                const float* __restrict__ gW1,
                const float* __restrict__ gW2)
{
    __shared__ uint4 sB[2][4][8][32];   // [matrix][kc][ntile][lane] = {bhi0,bhi1,blo0,blo1} 32 KB

    const int tid = threadIdx.x;
    for (int e = tid; e < 2048; e += THREADS) {
        int m = e >> 10, kc = (e >> 8) & 3, n = (e >> 5) & 7, ln = e & 31;
        int tg = ln & 3, gg = ln >> 2;
        const float* W = m ? gW2 : gW1;
        int k0 = kc * 16 + tg * 2, c = n * 8 + gg;
        uint32_t h0, l0, h1, l1;
        split_pair(W[k0*FD + c],     W[(k0+1)*FD + c], h0, l0);
        split_pair(W[(k0+8)*FD + c], W[(k0+9)*FD + c], h1, l1);
        sB[m][kc][n][ln] = make_uint4(h0, h1, l0, l1);
    }
    __syncthreads();

    const int gw = (tid >> 5) * GRID1 + blockIdx.x;   // transposed tile map
    if (gw >= NTILES) return;
    const int lane = tid & 31, tig = lane & 3, g = lane >> 2;
    const int tok0 = gw * 32;                 // 32 | 2048 -> warp never straddles a batch
    const int t0 = tok0 & (TOKT - 1);
    const float* bbase = he + (size_t)(tok0 - t0) * FD;

    // ---- A0 fragments from he rows ----
    uint32_t Ahi[2][4][4], Alo[2][4][4];
    #pragma unroll
    for (int mt = 0; mt < 2; ++mt)
        #pragma unroll
        for (int kc = 0; kc < 4; ++kc) {
            const float* p0 = he + (size_t)(tok0 + mt*16 + g)     * FD + kc*16 + tig*2;
            const float* p1 = he + (size_t)(tok0 + mt*16 + g + 8) * FD + kc*16 + tig*2;
            float2 v0 = *(const float2*)p0;
            float2 v1 = *(const float2*)p1;
            float2 v2 = *(const float2*)(p0 + 8);
            float2 v3 = *(const float2*)(p1 + 8);
            split_pair(v0.x, v0.y, Ahi[mt][kc][0], Alo[mt][kc][0]);
            split_pair(v1.x, v1.y, Ahi[mt][kc][1], Alo[mt][kc][1]);
            split_pair(v2.x, v2.y, Ahi[mt][kc][2], Alo[mt][kc][2]);
            split_pair(v3.x, v3.y, Ahi[mt][kc][3], Alo[mt][kc][3]);
        }

    float D[2][8][4];

    #pragma unroll 1
    for (int a = 0; a < AL; ++a) {
        // ---------- GEMM1: D = H @ W1  (3-term bf16 split) ----------
        #pragma unroll
        for (int kc = 0; kc < 4; ++kc)
            #pragma unroll
            for (int n = 0; n < 8; ++n) {
                uint4 b = sB[0][kc][n][lane];
                #pragma unroll
                for (int mt = 0; mt < 2; ++mt) {
                    if (kc == 0) mma_zero(D[mt][n], Ahi[mt][kc], b.x, b.y);
                    else         mma_acc (D[mt][n], Ahi[mt][kc], b.x, b.y);
                    mma_acc(D[mt][n], Ahi[mt][kc], b.z, b.w);   // Ahi * Blo
                    mma_acc(D[mt][n], Alo[mt][kc], b.x, b.y);   // Alo * Bhi
                }
            }
        // sigmoid + repack into A fragments (C layout == A half layout)
        #pragma unroll
        for (int mt = 0; mt < 2; ++mt)
            #pragma unroll
            for (int n = 0; n < 8; ++n)
                #pragma unroll
                for (int q = 0; q < 4; ++q)
                    D[mt][n][q] = sigmoidf_fast(D[mt][n][q]);
        #pragma unroll
        for (int mt = 0; mt < 2; ++mt)
            #pragma unroll
            for (int kc = 0; kc < 4; ++kc) {
                split_pair(D[mt][2*kc  ][0], D[mt][2*kc  ][1], Ahi[mt][kc][0], Alo[mt][kc][0]);
                split_pair(D[mt][2*kc  ][2], D[mt][2*kc  ][3], Ahi[mt][kc][1], Alo[mt][kc][1]);
                split_pair(D[mt][2*kc+1][0], D[mt][2*kc+1][1], Ahi[mt][kc][2], Alo[mt][kc][2]);
                split_pair(D[mt][2*kc+1][2], D[mt][2*kc+1][3], Ahi[mt][kc][3], Alo[mt][kc][3]);
            }

        // ---------- GEMM2: D = H_new @ W2 ----------
        #pragma unroll
        for (int kc = 0; kc < 4; ++kc)
            #pragma unroll
            for (int n = 0; n < 8; ++n) {
                uint4 b = sB[1][kc][n][lane];
                #pragma unroll
                for (int mt = 0; mt < 2; ++mt) {
                    if (kc == 0) mma_zero(D[mt][n], Ahi[mt][kc], b.x, b.y);
                    else         mma_acc (D[mt][n], Ahi[mt][kc], b.x, b.y);
                    mma_acc(D[mt][n], Ahi[mt][kc], b.z, b.w);
                    mma_acc(D[mt][n], Alo[mt][kc], b.x, b.y);
                }
            }
        // sigmoid -> Y (kept in D; not fed back)
        #pragma unroll
        for (int mt = 0; mt < 2; ++mt)
            #pragma unroll
            for (int n = 0; n < 8; ++n)
                #pragma unroll
                for (int q = 0; q < 4; ++q)
                    D[mt][n][q] = sigmoidf_fast(D[mt][n][q]);

        // ---------- scores: sc = <Y_token, he[j]> ----------
        #pragma unroll
        for (int mt = 0; mt < 2; ++mt)
            #pragma unroll
            for (int hf = 0; hf < 2; ++hf) {
                const int r = mt*16 + hf*8 + g;        // uniform within tig-group
                const int t = t0 + r;
                const int L = min(AL, max(t, 1));
                int j = t - L + a;
                if (j < 0) j = 0;
                const float* rp = bbase + (size_t)j * FD + tig * 2;
                float s = 0.f;
                #pragma unroll
                for (int n = 0; n < 8; ++n) {
                    float2 v = *(const float2*)(rp + n*8);
                    s = fmaf(D[mt][n][hf*2+0], v.x, s);
                    s = fmaf(D[mt][n][hf*2+1], v.y, s);
                }
                s += __shfl_xor_sync(0xffffffffu, s, 1);   // reduce over tig group
                s += __shfl_xor_sync(0xffffffffu, s, 2);
                if (tig == 0 && a < L)
                    g_scores[(size_t)(tok0 + r) * AL + a] = s;
            }
    }
}

// ---------------- Kernel 2: softmax + weighted gather (validated, unchanged) ----
__global__ void __launch_bounds__(TB2, 1)
attn_kernel(const float* __restrict__ he, float* __restrict__ out)
{
    __shared__ float srows[175 * RSTRIDE];

    const int tid   = threadIdx.x;
    const int t0g   = blockIdx.x * TB2;
    const int tseq0 = t0g & (TOKT - 1);
    const float* bbase = he + (size_t)(t0g - tseq0) * FD;

    const int r0    = max(0, tseq0 - AL);
    const int r1    = tseq0 + TB2 - 2;
    const int nrows = r1 - r0 + 1;

    {
        const float4* src = (const float4*)(bbase + (size_t)r0 * FD);
        float4* dst = (float4*)srows;
        for (int i = tid; i < nrows * 16; i += TB2) {
            int r = i >> 4, q = i & 15;
            dst[r * 17 + q] = src[r * 16 + q];
        }
    }
    __syncthreads();

    const int g = t0g + tid;
    const int t = tseq0 + tid;
    const int L = min(AL, max(t, 1));
    const float* scp = g_scores + (size_t)g * AL;

    float s[AL];
    #pragma unroll
    for (int a = 0; a < AL; ++a) {
        float v = scp[a];
        s[a] = (a < L) ? v : -1e30f;
    }
    float m = -1e30f;
    #pragma unroll
    for (int a = 0; a < AL; ++a) m = fmaxf(m, s[a]);

    ull cpair[FD / 2];
    #pragma unroll
    for (int p = 0; p < FD / 2; ++p) cpair[p] = 0ull;
    float ssum = 0.f;

    #pragma unroll 4
    for (int a = 0; a < AL; ++a) {
        float p = __expf(s[a] - m);
        ssum += p;
        int j = t - L + a;
        j = min(max(j, 0), r1);
        const ulonglong2* rp = (const ulonglong2*)(srows + (j - r0) * RSTRIDE);
        ull pp = pack2(p, p);
        #pragma unroll
        for (int q = 0; q < 16; ++q) {
            ulonglong2 v = rp[q];
            ffma2(cpair[2*q],   pp, v.x);
            ffma2(cpair[2*q+1], pp, v.y);
        }
    }

    const float inv = __fdividef(1.0f, ssum);
    float4* o = (float4*)(out + (size_t)g * FD);
    #pragma unroll
    for (int i = 0; i < FD / 4; ++i) {
        float x0, y0, x1, y1;
        unpack2(cpair[2*i],   x0, y0);
        unpack2(cpair[2*i+1], x1, y1);
        float4 v;
        v.x = x0 * inv; v.y = y0 * inv; v.z = x1 * inv; v.w = y1 * inv;
        o[i] = v;
    }
}

extern "C" void kernel_launch(void* const* d_in, const int* in_sizes, int n_in,
                              void* d_out, int out_size)
{
    const float* he = (const float*)d_in[0];   // (16, 2048, 64) f32
    const float* W1 = (const float*)d_in[1];   // (64, 64) f32
    const float* W2 = (const float*)d_in[2];   // (64, 64) f32
    float* out = (float*)d_out;                // (16, 2048, 64) f32

    scan_mma_kernel<<<GRID1, THREADS>>>(he, W1, W2);
    attn_kernel<<<NTOK / TB2, TB2>>>(he, out);
}

// round 9
// speedup vs baseline: 4.1697x; 1.0018x over previous
#include <cuda_runtime.h>
#include <cuda_bf16.h>
#include <cstdint>

#define NTOK  32768
#define TOKT  2048
#define FD    64
#define AL    48
#define THREADS 256
#define GRID1 148
#define NTILES (NTOK / 32)     // 1024 warp tiles

#define TB2    128
#define RSTRIDE 68

typedef unsigned long long ull;

__device__ float g_scores[(size_t)NTOK * AL];

// ---------------- helpers ----------------
__device__ __forceinline__ float sigmoidf_fast(float x) {
    return __fdividef(1.0f, 1.0f + __expf(-x));
}
__device__ __forceinline__ uint32_t pack_bf16x2(float lo, float hi) {
    uint32_t r;
    asm("cvt.rn.bf16x2.f32 %0, %1, %2;" : "=r"(r) : "f"(hi), "f"(lo));
    return r;
}
__device__ __forceinline__ float bf_lo(uint32_t p) { return __uint_as_float(p << 16); }
__device__ __forceinline__ float bf_hi(uint32_t p) { return __uint_as_float(p & 0xFFFF0000u); }

__device__ __forceinline__ void split_pair(float d0, float d1, uint32_t& hi, uint32_t& lo) {
    hi = pack_bf16x2(d0, d1);
    lo = pack_bf16x2(d0 - bf_lo(hi), d1 - bf_hi(hi));
}

__device__ __forceinline__ void mma_acc(float* d, const uint32_t* a, uint32_t b0, uint32_t b1) {
    asm volatile("mma.sync.aligned.m16n8k16.row.col.f32.bf16.bf16.f32 "
        "{%0,%1,%2,%3}, {%4,%5,%6,%7}, {%8,%9}, {%0,%1,%2,%3};"
        : "+f"(d[0]), "+f"(d[1]), "+f"(d[2]), "+f"(d[3])
        : "r"(a[0]), "r"(a[1]), "r"(a[2]), "r"(a[3]), "r"(b0), "r"(b1));
}
__device__ __forceinline__ void mma_zero(float* d, const uint32_t* a, uint32_t b0, uint32_t b1) {
    asm volatile("mma.sync.aligned.m16n8k16.row.col.f32.bf16.bf16.f32 "
        "{%0,%1,%2,%3}, {%4,%5,%6,%7}, {%8,%9}, {%10,%10,%10,%10};"
        : "=f"(d[0]), "=f"(d[1]), "=f"(d[2]), "=f"(d[3])
        : "r"(a[0]), "r"(a[1]), "r"(a[2]), "r"(a[3]), "r"(b0), "r"(b1), "f"(0.0f));
}

__device__ __forceinline__ ull pack2(float x, float y) {
    ull r; asm("mov.b64 %0, {%1, %2};" : "=l"(r) : "f"(x), "f"(y)); return r;
}
__device__ __forceinline__ void unpack2(ull v, float& x, float& y) {
    asm("mov.b64 {%0, %1}, %2;" : "=f"(x), "=f"(y) : "l"(v));
}
__device__ __forceinline__ void ffma2(ull& d, ull a, ull b) {
    asm("fma.rn.f32x2 %0, %1, %2, %0;" : "+l"(d) : "l"(a), "l"(b));
}

// ---------------- Kernel 1: recurrent scan via mma.sync bf16x3 ----------------
// warp owns 32 consecutive tokens; H lives in A fragments (hi+lo bf16).
// 3-term split issued as PASSES over all 16 accumulators -> RAW distance 16 MMAs.
__global__ void __launch_bounds__(THREADS, 1)
scan_mma_kernel(const float* __restrict__ he,
                const float* __restrict__ gW1,
                const float* __restrict__ gW2)
{
    __shared__ uint4 sB[2][4][8][32];   // [matrix][kc][ntile][lane] = {bhi0,bhi1,blo0,blo1}

    const int tid = threadIdx.x;
    for (int e = tid; e < 2048; e += THREADS) {
        int m = e >> 10, kc = (e >> 8) & 3, n = (e >> 5) & 7, ln = e & 31;
        int tg = ln & 3, gg = ln >> 2;
        const float* W = m ? gW2 : gW1;
        int k0 = kc * 16 + tg * 2, c = n * 8 + gg;
        uint32_t h0, l0, h1, l1;
        split_pair(W[k0*FD + c],     W[(k0+1)*FD + c], h0, l0);
        split_pair(W[(k0+8)*FD + c], W[(k0+9)*FD + c], h1, l1);
        sB[m][kc][n][ln] = make_uint4(h0, h1, l0, l1);
    }
    __syncthreads();

    const int gw = (tid >> 5) * GRID1 + blockIdx.x;   // transposed tile map
    if (gw >= NTILES) return;
    const int lane = tid & 31, tig = lane & 3, g = lane >> 2;
    const int tok0 = gw * 32;
    const int t0 = tok0 & (TOKT - 1);
    const float* bbase = he + (size_t)(tok0 - t0) * FD;

    // ---- A0 fragments from he rows ----
    uint32_t Ahi[2][4][4], Alo[2][4][4];
    #pragma unroll
    for (int mt = 0; mt < 2; ++mt)
        #pragma unroll
        for (int kc = 0; kc < 4; ++kc) {
            const float* p0 = he + (size_t)(tok0 + mt*16 + g)     * FD + kc*16 + tig*2;
            const float* p1 = he + (size_t)(tok0 + mt*16 + g + 8) * FD + kc*16 + tig*2;
            float2 v0 = *(const float2*)p0;
            float2 v1 = *(const float2*)p1;
            float2 v2 = *(const float2*)(p0 + 8);
            float2 v3 = *(const float2*)(p1 + 8);
            split_pair(v0.x, v0.y, Ahi[mt][kc][0], Alo[mt][kc][0]);
            split_pair(v1.x, v1.y, Ahi[mt][kc][1], Alo[mt][kc][1]);
            split_pair(v2.x, v2.y, Ahi[mt][kc][2], Alo[mt][kc][2]);
            split_pair(v3.x, v3.y, Ahi[mt][kc][3], Alo[mt][kc][3]);
        }

    float D[2][8][4];

    #pragma unroll 1
    for (int a = 0; a < AL; ++a) {
        // ---------- GEMM1: D = H @ W1  (3 passes per kc over 16 accumulators) ----------
        #pragma unroll
        for (int kc = 0; kc < 4; ++kc) {
            uint4 B[8];
            #pragma unroll
            for (int n = 0; n < 8; ++n) B[n] = sB[0][kc][n][lane];
            #pragma unroll
            for (int n = 0; n < 8; ++n)
                #pragma unroll
                for (int mt = 0; mt < 2; ++mt) {
                    if (kc == 0) mma_zero(D[mt][n], Ahi[mt][kc], B[n].x, B[n].y);
                    else         mma_acc (D[mt][n], Ahi[mt][kc], B[n].x, B[n].y);
                }
            #pragma unroll
            for (int n = 0; n < 8; ++n)
                #pragma unroll
                for (int mt = 0; mt < 2; ++mt)
                    mma_acc(D[mt][n], Ahi[mt][kc], B[n].z, B[n].w);   // Ahi * Blo
            #pragma unroll
            for (int n = 0; n < 8; ++n)
                #pragma unroll
                for (int mt = 0; mt < 2; ++mt)
                    mma_acc(D[mt][n], Alo[mt][kc], B[n].x, B[n].y);   // Alo * Bhi
        }
        // sigmoid + repack into A fragments (C layout == A half layout)
        #pragma unroll
        for (int mt = 0; mt < 2; ++mt)
            #pragma unroll
            for (int n = 0; n < 8; ++n)
                #pragma unroll
                for (int q = 0; q < 4; ++q)
                    D[mt][n][q] = sigmoidf_fast(D[mt][n][q]);
        #pragma unroll
        for (int mt = 0; mt < 2; ++mt)
            #pragma unroll
            for (int kc = 0; kc < 4; ++kc) {
                split_pair(D[mt][2*kc  ][0], D[mt][2*kc  ][1], Ahi[mt][kc][0], Alo[mt][kc][0]);
                split_pair(D[mt][2*kc  ][2], D[mt][2*kc  ][3], Ahi[mt][kc][1], Alo[mt][kc][1]);
                split_pair(D[mt][2*kc+1][0], D[mt][2*kc+1][1], Ahi[mt][kc][2], Alo[mt][kc][2]);
                split_pair(D[mt][2*kc+1][2], D[mt][2*kc+1][3], Ahi[mt][kc][3], Alo[mt][kc][3]);
            }

        // ---------- GEMM2: D = H_new @ W2  (same pass structure) ----------
        #pragma unroll
        for (int kc = 0; kc < 4; ++kc) {
            uint4 B[8];
            #pragma unroll
            for (int n = 0; n < 8; ++n) B[n] = sB[1][kc][n][lane];
            #pragma unroll
            for (int n = 0; n < 8; ++n)
                #pragma unroll
                for (int mt = 0; mt < 2; ++mt) {
                    if (kc == 0) mma_zero(D[mt][n], Ahi[mt][kc], B[n].x, B[n].y);
                    else         mma_acc (D[mt][n], Ahi[mt][kc], B[n].x, B[n].y);
                }
            #pragma unroll
            for (int n = 0; n < 8; ++n)
                #pragma unroll
                for (int mt = 0; mt < 2; ++mt)
                    mma_acc(D[mt][n], Ahi[mt][kc], B[n].z, B[n].w);
            #pragma unroll
            for (int n = 0; n < 8; ++n)
                #pragma unroll
                for (int mt = 0; mt < 2; ++mt)
                    mma_acc(D[mt][n], Alo[mt][kc], B[n].x, B[n].y);
        }
        // sigmoid -> Y
        #pragma unroll
        for (int mt = 0; mt < 2; ++mt)
            #pragma unroll
            for (int n = 0; n < 8; ++n)
                #pragma unroll
                for (int q = 0; q < 4; ++q)
                    D[mt][n][q] = sigmoidf_fast(D[mt][n][q]);

        // ---------- scores: sc = <Y_token, he[j]> ----------
        #pragma unroll
        for (int mt = 0; mt < 2; ++mt)
            #pragma unroll
            for (int hf = 0; hf < 2; ++hf) {
                const int r = mt*16 + hf*8 + g;
                const int t = t0 + r;
                const int L = min(AL, max(t, 1));
                int j = t - L + a;
                if (j < 0) j = 0;
                const float* rp = bbase + (size_t)j * FD + tig * 2;
                float s = 0.f;
                #pragma unroll
                for (int n = 0; n < 8; ++n) {
                    float2 v = *(const float2*)(rp + n*8);
                    s = fmaf(D[mt][n][hf*2+0], v.x, s);
                    s = fmaf(D[mt][n][hf*2+1], v.y, s);
                }
                s += __shfl_xor_sync(0xffffffffu, s, 1);
                s += __shfl_xor_sync(0xffffffffu, s, 2);
                if (tig == 0 && a < L)
                    g_scores[(size_t)(tok0 + r) * AL + a] = s;
            }
    }
}

// ---------------- Kernel 2: softmax + weighted gather (validated, unchanged) ----
__global__ void __launch_bounds__(TB2, 1)
attn_kernel(const float* __restrict__ he, float* __restrict__ out)
{
    __shared__ float srows[175 * RSTRIDE];

    const int tid   = threadIdx.x;
    const int t0g   = blockIdx.x * TB2;
    const int tseq0 = t0g & (TOKT - 1);
    const float* bbase = he + (size_t)(t0g - tseq0) * FD;

    const int r0    = max(0, tseq0 - AL);
    const int r1    = tseq0 + TB2 - 2;
    const int nrows = r1 - r0 + 1;

    {
        const float4* src = (const float4*)(bbase + (size_t)r0 * FD);
        float4* dst = (float4*)srows;
        for (int i = tid; i < nrows * 16; i += TB2) {
            int r = i >> 4, q = i & 15;
            dst[r * 17 + q] = src[r * 16 + q];
        }
    }
    __syncthreads();

    const int g = t0g + tid;
    const int t = tseq0 + tid;
    const int L = min(AL, max(t, 1));
    const float* scp = g_scores + (size_t)g * AL;

    float s[AL];
    #pragma unroll
    for (int a = 0; a < AL; ++a) {
        float v = scp[a];
        s[a] = (a < L) ? v : -1e30f;
    }
    float m = -1e30f;
    #pragma unroll
    for (int a = 0; a < AL; ++a) m = fmaxf(m, s[a]);

    ull cpair[FD / 2];
    #pragma unroll
    for (int p = 0; p < FD / 2; ++p) cpair[p] = 0ull;
    float ssum = 0.f;

    #pragma unroll 4
    for (int a = 0; a < AL; ++a) {
        float p = __expf(s[a] - m);
        ssum += p;
        int j = t - L + a;
        j = min(max(j, 0), r1);
        const ulonglong2* rp = (const ulonglong2*)(srows + (j - r0) * RSTRIDE);
        ull pp = pack2(p, p);
        #pragma unroll
        for (int q = 0; q < 16; ++q) {
            ulonglong2 v = rp[q];
            ffma2(cpair[2*q],   pp, v.x);
            ffma2(cpair[2*q+1], pp, v.y);
        }
    }

    const float inv = __fdividef(1.0f, ssum);
    float4* o = (float4*)(out + (size_t)g * FD);
    #pragma unroll
    for (int i = 0; i < FD / 4; ++i) {
        float x0, y0, x1, y1;
        unpack2(cpair[2*i],   x0, y0);
        unpack2(cpair[2*i+1], x1, y1);
        float4 v;
        v.x = x0 * inv; v.y = y0 * inv; v.z = x1 * inv; v.w = y1 * inv;
        o[i] = v;
    }
}

extern "C" void kernel_launch(void* const* d_in, const int* in_sizes, int n_in,
                              void* d_out, int out_size)
{
    const float* he = (const float*)d_in[0];   // (16, 2048, 64) f32
    const float* W1 = (const float*)d_in[1];   // (64, 64) f32
    const float* W2 = (const float*)d_in[2];   // (64, 64) f32
    float* out = (float*)d_out;                // (16, 2048, 64) f32

    scan_mma_kernel<<<GRID1, THREADS>>>(he, W1, W2);
    attn_kernel<<<NTOK / TB2, TB2>>>(he, out);
}

// round 11
// speedup vs baseline: 4.5639x; 1.0945x over previous
#include <cuda_runtime.h>
#include <cuda_bf16.h>
#include <cstdint>

#define NTOK  32768
#define TOKT  2048
#define FD    64
#define AL    48
#define THREADS 512
#define GRID1 148
#define NTILES (NTOK / 16)     // 2048 warp tiles (16 tokens each)

#define TB2    128
#define RSTRIDE 68

typedef unsigned long long ull;

__device__ float g_scores[(size_t)NTOK * AL];

// ---------------- helpers ----------------
__device__ __forceinline__ float sigmoidf_fast(float x) {
    return __fdividef(1.0f, 1.0f + __expf(-x));
}
__device__ __forceinline__ uint32_t pack_bf16x2(float lo, float hi) {
    uint32_t r;
    asm("cvt.rn.bf16x2.f32 %0, %1, %2;" : "=r"(r) : "f"(hi), "f"(lo));
    return r;
}
__device__ __forceinline__ float bf_lo(uint32_t p) { return __uint_as_float(p << 16); }
__device__ __forceinline__ float bf_hi(uint32_t p) { return __uint_as_float(p & 0xFFFF0000u); }

__device__ __forceinline__ void split_pair(float d0, float d1, uint32_t& hi, uint32_t& lo) {
    hi = pack_bf16x2(d0, d1);
    lo = pack_bf16x2(d0 - bf_lo(hi), d1 - bf_hi(hi));
}

__device__ __forceinline__ void mma_acc(float* d, const uint32_t* a, uint32_t b0, uint32_t b1) {
    asm volatile("mma.sync.aligned.m16n8k16.row.col.f32.bf16.bf16.f32 "
        "{%0,%1,%2,%3}, {%4,%5,%6,%7}, {%8,%9}, {%0,%1,%2,%3};"
        : "+f"(d[0]), "+f"(d[1]), "+f"(d[2]), "+f"(d[3])
        : "r"(a[0]), "r"(a[1]), "r"(a[2]), "r"(a[3]), "r"(b0), "r"(b1));
}
__device__ __forceinline__ void mma_zero(float* d, const uint32_t* a, uint32_t b0, uint32_t b1) {
    asm volatile("mma.sync.aligned.m16n8k16.row.col.f32.bf16.bf16.f32 "
        "{%0,%1,%2,%3}, {%4,%5,%6,%7}, {%8,%9}, {%10,%10,%10,%10};"
        : "=f"(d[0]), "=f"(d[1]), "=f"(d[2]), "=f"(d[3])
        : "r"(a[0]), "r"(a[1]), "r"(a[2]), "r"(a[3]), "r"(b0), "r"(b1), "f"(0.0f));
}

__device__ __forceinline__ ull pack2(float x, float y) {
    ull r; asm("mov.b64 %0, {%1, %2};" : "=l"(r) : "f"(x), "f"(y)); return r;
}
__device__ __forceinline__ void unpack2(ull v, float& x, float& y) {
    asm("mov.b64 {%0, %1}, %2;" : "=f"(x), "=f"(y) : "l"(v));
}
__device__ __forceinline__ void ffma2(ull& d, ull a, ull b) {
    asm("fma.rn.f32x2 %0, %1, %2, %0;" : "+l"(d) : "l"(a), "l"(b));
}

// ---------------- Kernel 1: recurrent scan via mma.sync bf16x3 ----------------
// 16 tokens per warp, 16 warps per CTA (512 thr) -> 4 warps/SMSP for
// phase overlap (GEMM vs sigmoid/repack). H lives in A fragments (hi+lo bf16).
__global__ void __launch_bounds__(THREADS, 1)
scan_mma_kernel(const float* __restrict__ he,
                const float* __restrict__ gW1,
                const float* __restrict__ gW2)
{
    __shared__ uint4 sB[2][4][8][32];   // [matrix][kc][ntile][lane] = {bhi0,bhi1,blo0,blo1}

    const int tid = threadIdx.x;
    for (int e = tid; e < 2048; e += THREADS) {
        int m = e >> 10, kc = (e >> 8) & 3, n = (e >> 5) & 7, ln = e & 31;
        int tg = ln & 3, gg = ln >> 2;
        const float* W = m ? gW2 : gW1;
        int k0 = kc * 16 + tg * 2, c = n * 8 + gg;
        uint32_t h0, l0, h1, l1;
        split_pair(W[k0*FD + c],     W[(k0+1)*FD + c], h0, l0);
        split_pair(W[(k0+8)*FD + c], W[(k0+9)*FD + c], h1, l1);
        sB[m][kc][n][ln] = make_uint4(h0, h1, l0, l1);
    }
    __syncthreads();

    const int gw = (tid >> 5) * GRID1 + blockIdx.x;   // transposed tile map
    if (gw >= NTILES) return;
    const int lane = tid & 31, tig = lane & 3, g = lane >> 2;
    const int tok0 = gw * 16;                 // 16 | 2048 -> warp never straddles a batch
    const int t0 = tok0 & (TOKT - 1);
    const float* bbase = he + (size_t)(tok0 - t0) * FD;

    // ---- A0 fragments from he rows ----
    uint32_t Ahi[4][4], Alo[4][4];
    #pragma unroll
    for (int kc = 0; kc < 4; ++kc) {
        const float* p0 = he + (size_t)(tok0 + g)     * FD + kc*16 + tig*2;
        const float* p1 = he + (size_t)(tok0 + g + 8) * FD + kc*16 + tig*2;
        float2 v0 = *(const float2*)p0;
        float2 v1 = *(const float2*)p1;
        float2 v2 = *(const float2*)(p0 + 8);
        float2 v3 = *(const float2*)(p1 + 8);
        split_pair(v0.x, v0.y, Ahi[kc][0], Alo[kc][0]);
        split_pair(v1.x, v1.y, Ahi[kc][1], Alo[kc][1]);
        split_pair(v2.x, v2.y, Ahi[kc][2], Alo[kc][2]);
        split_pair(v3.x, v3.y, Ahi[kc][3], Alo[kc][3]);
    }

    float D[8][4];

    #pragma unroll 1
    for (int a = 0; a < AL; ++a) {
        // ---------- GEMM1: D = H @ W1  (bf16 3-term split) ----------
        #pragma unroll
        for (int kc = 0; kc < 4; ++kc)
            #pragma unroll
            for (int n = 0; n < 8; ++n) {
                uint4 b = sB[0][kc][n][lane];
                if (kc == 0) mma_zero(D[n], Ahi[kc], b.x, b.y);
                else         mma_acc (D[n], Ahi[kc], b.x, b.y);
                mma_acc(D[n], Ahi[kc], b.z, b.w);   // Ahi * Blo
                mma_acc(D[n], Alo[kc], b.x, b.y);   // Alo * Bhi
            }
        // sigmoid + repack into A fragments (C layout == A half layout)
        #pragma unroll
        for (int n = 0; n < 8; ++n)
            #pragma unroll
            for (int q = 0; q < 4; ++q)
                D[n][q] = sigmoidf_fast(D[n][q]);
        #pragma unroll
        for (int kc = 0; kc < 4; ++kc) {
            split_pair(D[2*kc  ][0], D[2*kc  ][1], Ahi[kc][0], Alo[kc][0]);
            split_pair(D[2*kc  ][2], D[2*kc  ][3], Ahi[kc][1], Alo[kc][1]);
            split_pair(D[2*kc+1][0], D[2*kc+1][1], Ahi[kc][2], Alo[kc][2]);
            split_pair(D[2*kc+1][2], D[2*kc+1][3], Ahi[kc][3], Alo[kc][3]);
        }

        // ---------- GEMM2: D = H_new @ W2 ----------
        #pragma unroll
        for (int kc = 0; kc < 4; ++kc)
            #pragma unroll
            for (int n = 0; n < 8; ++n) {
                uint4 b = sB[1][kc][n][lane];
                if (kc == 0) mma_zero(D[n], Ahi[kc], b.x, b.y);
                else         mma_acc (D[n], Ahi[kc], b.x, b.y);
                mma_acc(D[n], Ahi[kc], b.z, b.w);
                mma_acc(D[n], Alo[kc], b.x, b.y);
            }
        // sigmoid -> Y
        #pragma unroll
        for (int n = 0; n < 8; ++n)
            #pragma unroll
            for (int q = 0; q < 4; ++q)
                D[n][q] = sigmoidf_fast(D[n][q]);

        // ---------- scores: sc = <Y_token, he[j]> ----------
        #pragma unroll
        for (int hf = 0; hf < 2; ++hf) {
            const int r = hf*8 + g;
            const int t = t0 + r;
            const int L = min(AL, max(t, 1));
            int j = t - L + a;
            if (j < 0) j = 0;
            const float* rp = bbase + (size_t)j * FD + tig * 2;
            float s = 0.f;
            #pragma unroll
            for (int n = 0; n < 8; ++n) {
                float2 v = *(const float2*)(rp + n*8);
                s = fmaf(D[n][hf*2+0], v.x, s);
                s = fmaf(D[n][hf*2+1], v.y, s);
            }
            s += __shfl_xor_sync(0xffffffffu, s, 1);
            s += __shfl_xor_sync(0xffffffffu, s, 2);
            if (tig == 0 && a < L)
                g_scores[(size_t)(tok0 + r) * AL + a] = s;
        }
    }
}

// ---------------- Kernel 2: softmax + weighted gather (validated, unchanged) ----
__global__ void __launch_bounds__(TB2, 1)
attn_kernel(const float* __restrict__ he, float* __restrict__ out)
{
    __shared__ float srows[175 * RSTRIDE];

    const int tid   = threadIdx.x;
    const int t0g   = blockIdx.x * TB2;
    const int tseq0 = t0g & (TOKT - 1);
    const float* bbase = he + (size_t)(t0g - tseq0) * FD;

    const int r0    = max(0, tseq0 - AL);
    const int r1    = tseq0 + TB2 - 2;
    const int nrows = r1 - r0 + 1;

    {
        const float4* src = (const float4*)(bbase + (size_t)r0 * FD);
        float4* dst = (float4*)srows;
        for (int i = tid; i < nrows * 16; i += TB2) {
            int r = i >> 4, q = i & 15;
            dst[r * 17 + q] = src[r * 16 + q];
        }
    }
    __syncthreads();

    const int g = t0g + tid;
    const int t = tseq0 + tid;
    const int L = min(AL, max(t, 1));
    const float* scp = g_scores + (size_t)g * AL;

    float s[AL];
    #pragma unroll
    for (int a = 0; a < AL; ++a) {
        float v = scp[a];
        s[a] = (a < L) ? v : -1e30f;
    }
    float m = -1e30f;
    #pragma unroll
    for (int a = 0; a < AL; ++a) m = fmaxf(m, s[a]);

    ull cpair[FD / 2];
    #pragma unroll
    for (int p = 0; p < FD / 2; ++p) cpair[p] = 0ull;
    float ssum = 0.f;

    #pragma unroll 4
    for (int a = 0; a < AL; ++a) {
        float p = __expf(s[a] - m);
        ssum += p;
        int j = t - L + a;
        j = min(max(j, 0), r1);
        const ulonglong2* rp = (const ulonglong2*)(srows + (j - r0) * RSTRIDE);
        ull pp = pack2(p, p);
        #pragma unroll
        for (int q = 0; q < 16; ++q) {
            ulonglong2 v = rp[q];
            ffma2(cpair[2*q],   pp, v.x);
            ffma2(cpair[2*q+1], pp, v.y);
        }
    }

    const float inv = __fdividef(1.0f, ssum);
    float4* o = (float4*)(out + (size_t)g * FD);
    #pragma unroll
    for (int i = 0; i < FD / 4; ++i) {
        float x0, y0, x1, y1;
        unpack2(cpair[2*i],   x0, y0);
        unpack2(cpair[2*i+1], x1, y1);
        float4 v;
        v.x = x0 * inv; v.y = y0 * inv; v.z = x1 * inv; v.w = y1 * inv;
        o[i] = v;
    }
}

extern "C" void kernel_launch(void* const* d_in, const int* in_sizes, int n_in,
                              void* d_out, int out_size)
{
    const float* he = (const float*)d_in[0];   // (16, 2048, 64) f32
    const float* W1 = (const float*)d_in[1];   // (64, 64) f32
    const float* W2 = (const float*)d_in[2];   // (64, 64) f32
    float* out = (float*)d_out;                // (16, 2048, 64) f32

    scan_mma_kernel<<<GRID1, THREADS>>>(he, W1, W2);
    attn_kernel<<<NTOK / TB2, TB2>>>(he, out);
}